// round 14
// baseline (speedup 1.0000x reference)
#include <cuda_runtime.h>
#include <cuda_bf16.h>
#include <math.h>

#define Hs   128
#define Ws   128
#define Cs   64
#define Os   64
#define HW   16384
#define Q    576          // Cs * 9
#define NP   24           // padded N for offset conv

typedef unsigned long long u64;
typedef unsigned int u32;

// channel-last transpose of x: [b][y][x][c]
__device__ __align__(16) float g_xt[4 * HW * 64];
// bf16-split deform weights: [k][o][c]
__device__ __align__(16) __nv_bfloat16 g_whi[9 * 64 * 64];
__device__ __align__(16) __nv_bfloat16 g_wlo[9 * 64 * 64];
// bf16-split offset-conv weights: [k][n(24)][c]
__device__ __align__(16) __nv_bfloat16 g_wohi[9 * NP * 64];
__device__ __align__(16) __nv_bfloat16 g_wolo[9 * NP * 64];

// ---------------- helpers ----------------
__device__ __forceinline__ u64 pack2(float lo, float hi) {
    u64 r;
    asm("mov.b64 %0, {%1, %2};" : "=l"(r) : "f"(lo), "f"(hi));
    return r;
}
__device__ __forceinline__ void unpack2(u64 v, float& lo, float& hi) {
    asm("mov.b64 {%0, %1}, %2;" : "=f"(lo), "=f"(hi) : "l"(v));
}
__device__ __forceinline__ u64 pack64(u32 a, u32 b) {
    return (u64)a | ((u64)b << 32);
}
__device__ __forceinline__ u32 smem_u32(const void* p) {
    u32 a;
    asm("{ .reg .u64 t; cvta.to.shared.u64 t, %1; cvt.u32.u64 %0, t; }"
        : "=r"(a) : "l"(p));
    return a;
}

#define SMEM_SWIZZLE_128B(o) ((o) ^ (((o) >> 3) & 0x70))

__device__ __forceinline__ void hmma(float* d, const u32* a, const u32* b) {
    asm volatile(
        "mma.sync.aligned.m16n8k16.row.col.f32.bf16.bf16.f32 "
        "{%0,%1,%2,%3}, {%4,%5,%6,%7}, {%8,%9}, {%0,%1,%2,%3};"
        : "+f"(d[0]), "+f"(d[1]), "+f"(d[2]), "+f"(d[3])
        : "r"(a[0]), "r"(a[1]), "r"(a[2]), "r"(a[3]), "r"(b[0]), "r"(b[1]));
}

__device__ __forceinline__ void ldsm_x4(u32* d, u32 addr) {
    asm volatile("ldmatrix.sync.aligned.m8n8.x4.shared.b16 {%0,%1,%2,%3}, [%4];"
        : "=r"(d[0]), "=r"(d[1]), "=r"(d[2]), "=r"(d[3]) : "r"(addr));
}
__device__ __forceinline__ void ldsm_x2(u32* d, u32 addr) {
    asm volatile("ldmatrix.sync.aligned.m8n8.x2.shared.b16 {%0,%1}, [%2];"
        : "=r"(d[0]), "=r"(d[1]) : "r"(addr));
}

__device__ __forceinline__ void split_bf16(float v, __nv_bfloat16& h, __nv_bfloat16& l) {
    h = __float2bfloat16(v);
    l = __float2bfloat16(v - __bfloat162float(h));
}
__device__ __forceinline__ void split2(float se, float so, u32& hh, u32& ll) {
    __nv_bfloat16 he, le, ho, lo2;
    split_bf16(se, he, le);
    split_bf16(so, ho, lo2);
    hh = (u32)__bfloat16_as_ushort(he) | ((u32)__bfloat16_as_ushort(ho) << 16);
    ll = (u32)__bfloat16_as_ushort(le) | ((u32)__bfloat16_as_ushort(lo2) << 16);
}

// ================= Kernel A: NCHW -> NHWC transpose of x =================
__global__ void __launch_bounds__(256)
transpose_kernel(const float* __restrict__ x) {
    __shared__ float tile[64 * 129];
    int row = blockIdx.x;               // b*128 + y
    int y = row & 127, b = row >> 7;
    const float* xb = x + (size_t)b * Cs * HW + y * Ws;
    int t = threadIdx.x;
    int w0 = t & 127, c0 = t >> 7;
#pragma unroll
    for (int i = 0; i < 32; i++) {
        int c = c0 + i * 2;
        tile[c * 129 + w0] = __ldg(xb + (size_t)c * HW + w0);
    }
    __syncthreads();
    float4* dst = (float4*)(g_xt + (size_t)row * 128 * 64);
#pragma unroll
    for (int i = 0; i < 8; i++) {
        int idx = t + i * 256;          // float4 index: idx = w*16 + cq
        int w = idx >> 4, cq = (idx & 15) * 4;
        float4 v;
        v.x = tile[cq * 129 + w];
        v.y = tile[(cq + 1) * 129 + w];
        v.z = tile[(cq + 2) * 129 + w];
        v.w = tile[(cq + 3) * 129 + w];
        dst[idx] = v;
    }
}

// ================= Kernel 0: split both weight sets to bf16 hi/lo =================
__global__ void wsplit_kernel(const float* __restrict__ wd,
                              const float* __restrict__ wo) {
    int i = blockIdx.x * 256 + threadIdx.x;
    if (i < 9 * 64 * 64) {
        int k = i >> 12;
        int r = i & 4095;
        int o = r >> 6;
        int c = r & 63;
        float v = wd[o * Q + c * 9 + k];
        __nv_bfloat16 h, l;
        split_bf16(v, h, l);
        g_whi[i] = h;
        g_wlo[i] = l;
    } else if (i < 9 * 64 * 64 + 9 * NP * 64) {
        int j = i - 9 * 64 * 64;
        int k = j / (NP * 64);
        int r = j - k * (NP * 64);
        int n = r >> 6;
        int c = r & 63;
        float v = (n < 18) ? wo[n * Q + c * 9 + k] : 0.0f;
        __nv_bfloat16 h, l;
        split_bf16(v, h, l);
        g_wohi[j] = h;
        g_wolo[j] = l;
    }
}

// ================= Fused kernel: offset conv + deformable conv =================
static constexpr int SM_SHI = 0;
static constexpr int SM_SLO = 16384;
static constexpr int SM_WHI = 32768;
static constexpr int SM_WLO = 40960;
static constexpr int SM_OFF = 49152;
static constexpr int SM_TOT = 58368;

__global__ void __launch_bounds__(256, 3)
fused_deform_kernel(const float* __restrict__ bo,
                    const float* __restrict__ bd,
                    float* __restrict__ out) {
    extern __shared__ __align__(1024) char smem[];
    u32 sb = smem_u32(smem);
    u64* offbuf = (u64*)(smem + SM_OFF);     // [9][128]

    int t    = threadIdx.x;
    int wid  = t >> 5;
    int lane = t & 31;
    int g    = lane >> 2;
    int tig  = lane & 3;

    int tile = blockIdx.x;
    int h = tile & 127;
    int b = tile >> 7;
    const float* xt = g_xt + (size_t)b * HW * 64;   // [y][x][c]

    int m0 = wid * 16;
    int p0 = t >> 4;          // sampler pixel base (0..15)
    int q4 = (t & 15) * 4;    // channel quad -> channel index

    int lr  = lane & 7;
    int lmi = lane >> 3;
    u32 aRow = (u32)((m0 + (lmi & 1) * 8 + lr) * 128);
    u32 aKof = (u32)((lmi >> 1) * 16);
    u32 bRow = (u32)(((lmi >> 1) * 8 + lr) * 128);
    u32 bKof = (u32)((lmi & 1) * 16);
    u32 b2Row = (u32)((16 + lr) * 128);
    u32 b2Kof = (u32)((lmi & 1) * 16);

    // ============ PHASE 1: offset conv (M=128, N=24, K=576) ============
    {
        float acc[3][4];
#pragma unroll
        for (int nt = 0; nt < 3; nt++)
#pragma unroll
            for (int j = 0; j < 4; j++) acc[nt][j] = 0.0f;

#pragma unroll 1
        for (int k = 0; k < 9; k++) {
            if (t < 192) {
                int n  = t >> 3;
                int c8 = t & 7;
                u32 dst = SMEM_SWIZZLE_128B((u32)(n * 128 + c8 * 16));
                *(uint4*)(smem + SM_WHI + dst) =
                    *(const uint4*)(g_wohi + k * NP * 64 + n * 64 + c8 * 8);
                *(uint4*)(smem + SM_WLO + dst) =
                    *(const uint4*)(g_wolo + k * NP * 64 + n * 64 + c8 * 8);
            }

            {
                int kh = k / 3, kw = k - kh * 3;
                int iy = h - 1 + kh;
                bool yok = (iy >= 0 && iy < Hs);
                int cy = min(max(iy, 0), Hs - 1);
                const float* xrow = xt + (size_t)cy * 128 * 64;
#pragma unroll
                for (int it = 0; it < 8; it++) {
                    int p = p0 + it * 16;
                    int ix = p - 1 + kw;
                    float vf = (yok && ix >= 0 && ix < Ws) ? 1.0f : 0.0f;
                    int cx = min(max(ix, 0), Ws - 1);
                    float4 v = *(const float4*)(xrow + cx * 64 + q4);
                    u32 hh0, ll0, hh1, ll1;
                    split2(v.x * vf, v.y * vf, hh0, ll0);
                    split2(v.z * vf, v.w * vf, hh1, ll1);
                    u32 off = SMEM_SWIZZLE_128B((u32)(p * 128 + q4 * 2));
                    *(u64*)(smem + SM_SHI + off) = pack64(hh0, hh1);
                    *(u64*)(smem + SM_SLO + off) = pack64(ll0, ll1);
                }
            }
            __syncthreads();

#pragma unroll
            for (int ks = 0; ks < 4; ks++) {
                u32 kb = (u32)(ks * 32);
                u32 ah[4], al[4];
                ldsm_x4(ah, sb + SM_SHI + SMEM_SWIZZLE_128B(aRow + kb + aKof));
                ldsm_x4(al, sb + SM_SLO + SMEM_SWIZZLE_128B(aRow + kb + aKof));
                u32 bh[4], bl[4];
                ldsm_x4(bh, sb + SM_WHI + SMEM_SWIZZLE_128B(bRow + kb + bKof));
                ldsm_x4(bl, sb + SM_WLO + SMEM_SWIZZLE_128B(bRow + kb + bKof));
                hmma(acc[0], ah, bh);     hmma(acc[0], ah, bl);     hmma(acc[0], al, bh);
                hmma(acc[1], ah, bh + 2); hmma(acc[1], ah, bl + 2); hmma(acc[1], al, bh + 2);
                u32 ch[2], cl[2];
                ldsm_x2(ch, sb + SM_WHI + SMEM_SWIZZLE_128B(b2Row + kb + b2Kof));
                ldsm_x2(cl, sb + SM_WLO + SMEM_SWIZZLE_128B(b2Row + kb + b2Kof));
                hmma(acc[2], ah, ch);     hmma(acc[2], ah, cl);     hmma(acc[2], al, ch);
            }
            __syncthreads();
        }

        float* O = (float*)smem;       // [24 n][132 m]
#pragma unroll
        for (int nt = 0; nt < 3; nt++) {
            int n = nt * 8 + tig * 2;
            int m = m0 + g;
            O[n * 132 + m]            = acc[nt][0];
            O[(n + 1) * 132 + m]      = acc[nt][1];
            O[n * 132 + m + 8]        = acc[nt][2];
            O[(n + 1) * 132 + m + 8]  = acc[nt][3];
        }
        __syncthreads();

        for (int i = t; i < 9 * 128; i += 256) {
            int k2 = i >> 7;
            int m  = i & 127;
            float dy = O[(2 * k2) * 132 + m]     + __ldg(bo + 2 * k2);
            float dx = O[(2 * k2 + 1) * 132 + m] + __ldg(bo + 2 * k2 + 1);
            offbuf[k2 * 128 + m] = pack2(dy, dx);
        }
        __syncthreads();
    }

    // ============ PHASE 2: deformable conv (M=128, N=64, K=576) ============
    {
        float acc[8][4];
#pragma unroll
        for (int nt = 0; nt < 8; nt++)
#pragma unroll
            for (int j = 0; j < 4; j++) acc[nt][j] = 0.0f;

#pragma unroll 1
        for (int k = 0; k < 9; k++) {
            for (int j = t; j < 512; j += 256) {
                int n  = j >> 3;
                int c8 = j & 7;
                u32 dst = SMEM_SWIZZLE_128B((u32)(n * 128 + c8 * 16));
                *(uint4*)(smem + SM_WHI + dst) =
                    *(const uint4*)(g_whi + k * 4096 + n * 64 + c8 * 8);
                *(uint4*)(smem + SM_WLO + dst) =
                    *(const uint4*)(g_wlo + k * 4096 + n * 64 + c8 * 8);
            }

            {
                int kh = k / 3, kw = k - kh * 3;
                float hbase = (float)(h - 1 + kh);
#pragma unroll
                for (int it = 0; it < 8; it++) {
                    int p = p0 + it * 16;
                    float dlo, dhi;
                    unpack2(offbuf[k * 128 + p], dlo, dhi);
                    float py = hbase + dlo;
                    float px = (float)(p - 1 + kw) + dhi;
                    float y0f = floorf(py), x0f = floorf(px);
                    int y0 = (int)y0f, x0 = (int)x0f;
                    int y1 = y0 + 1,   x1 = x0 + 1;
                    float wy1 = py - y0f, wy0 = 1.0f - wy1;
                    float wx1 = px - x0f, wx0 = 1.0f - wx1;
                    float vy0 = (y0 >= 0 && y0 < Hs) ? 1.0f : 0.0f;
                    float vy1 = (y1 >= 0 && y1 < Hs) ? 1.0f : 0.0f;
                    float vx0 = (x0 >= 0 && x0 < Ws) ? 1.0f : 0.0f;
                    float vx1 = (x1 >= 0 && x1 < Ws) ? 1.0f : 0.0f;
                    float w00 = wy0 * wx0 * vy0 * vx0;
                    float w01 = wy0 * wx1 * vy0 * vx1;
                    float w10 = wy1 * wx0 * vy1 * vx0;
                    float w11 = wy1 * wx1 * vy1 * vx1;
                    int cy0 = min(max(y0, 0), Hs - 1), cy1 = min(max(y1, 0), Hs - 1);
                    int cx0 = min(max(x0, 0), Ws - 1), cx1 = min(max(x1, 0), Ws - 1);
                    // pairwise tap combine: row y0 first, then row y1 (peak 2 float4)
                    const float* r0p = xt + (size_t)(cy0 * 128) * 64 + q4;
                    float4 ta = *(const float4*)(r0p + cx0 * 64);
                    float4 tb = *(const float4*)(r0p + cx1 * 64);
                    float s0 = fmaf(w00, ta.x, w01 * tb.x);
                    float s1 = fmaf(w00, ta.y, w01 * tb.y);
                    float s2 = fmaf(w00, ta.z, w01 * tb.z);
                    float s3 = fmaf(w00, ta.w, w01 * tb.w);
                    const float* r1p = xt + (size_t)(cy1 * 128) * 64 + q4;
                    ta = *(const float4*)(r1p + cx0 * 64);
                    tb = *(const float4*)(r1p + cx1 * 64);
                    s0 = fmaf(w10, ta.x, fmaf(w11, tb.x, s0));
                    s1 = fmaf(w10, ta.y, fmaf(w11, tb.y, s1));
                    s2 = fmaf(w10, ta.z, fmaf(w11, tb.z, s2));
                    s3 = fmaf(w10, ta.w, fmaf(w11, tb.w, s3));
                    u32 hh0, ll0, hh1, ll1;
                    split2(s0, s1, hh0, ll0);
                    split2(s2, s3, hh1, ll1);
                    u32 off = SMEM_SWIZZLE_128B((u32)(p * 128 + q4 * 2));
                    *(u64*)(smem + SM_SHI + off) = pack64(hh0, hh1);
                    *(u64*)(smem + SM_SLO + off) = pack64(ll0, ll1);
                }
            }
            __syncthreads();

#pragma unroll
            for (int ks = 0; ks < 4; ks++) {
                u32 kb = (u32)(ks * 32);
                u32 ah[4], al[4];
                ldsm_x4(ah, sb + SM_SHI + SMEM_SWIZZLE_128B(aRow + kb + aKof));
                ldsm_x4(al, sb + SM_SLO + SMEM_SWIZZLE_128B(aRow + kb + aKof));
#pragma unroll
                for (int p = 0; p < 4; p++) {
                    u32 bh[4], bl[4];
                    u32 boff = SMEM_SWIZZLE_128B((u32)(p * 2048) + bRow + kb + bKof);
                    ldsm_x4(bh, sb + SM_WHI + boff);
                    ldsm_x4(bl, sb + SM_WLO + boff);
                    hmma(acc[2 * p],     ah, bh);     hmma(acc[2 * p],     ah, bl);
                    hmma(acc[2 * p],     al, bh);
                    hmma(acc[2 * p + 1], ah, bh + 2); hmma(acc[2 * p + 1], ah, bl + 2);
                    hmma(acc[2 * p + 1], al, bh + 2);
                }
            }
            __syncthreads();
        }

        float* O = (float*)smem;       // [64 n][132 m]
#pragma unroll
        for (int nt = 0; nt < 8; nt++) {
            int n = nt * 8 + tig * 2;
            int m = m0 + g;
            O[n * 132 + m]            = acc[nt][0];
            O[(n + 1) * 132 + m]      = acc[nt][1];
            O[n * 132 + m + 8]        = acc[nt][2];
            O[(n + 1) * 132 + m + 8]  = acc[nt][3];
        }
        __syncthreads();

        float* ob = out + (size_t)b * Os * HW + h * 128;
        for (int i = t; i < 64 * 128; i += 256) {
            int o  = i >> 7;
            int w2 = i & 127;
            ob[(size_t)o * HW + w2] = O[o * 132 + w2] + __ldg(bd + o);
        }
    }
}

// ---------------- harness entry ----------------
extern "C" void kernel_launch(void* const* d_in, const int* in_sizes, int n_in,
                              void* d_out, int out_size) {
    const float* x  = (const float*)d_in[0];   // [4,64,128,128]
    const float* wo = (const float*)d_in[1];   // [18,64,3,3]
    const float* bo = (const float*)d_in[2];   // [18]
    const float* wd = (const float*)d_in[3];   // [64,64,3,3]
    const float* bd = (const float*)d_in[4];   // [64]
    float* out = (float*)d_out;                // [4,64,128,128]

    cudaFuncSetAttribute(fused_deform_kernel,
                         cudaFuncAttributeMaxDynamicSharedMemorySize, SM_TOT);

    transpose_kernel<<<512, 256>>>(x);
    wsplit_kernel<<<198, 256>>>(wd, wo);
    fused_deform_kernel<<<512, 256, SM_TOT>>>(bo, bd, out);
}

// round 15
// speedup vs baseline: 1.1158x; 1.1158x over previous
#include <cuda_runtime.h>
#include <cuda_bf16.h>
#include <math.h>

#define Hs   128
#define Ws   128
#define Cs   64
#define Os   64
#define HW   16384
#define Q    576          // Cs * 9
#define NP   24           // padded N for offset conv

typedef unsigned long long u64;
typedef unsigned int u32;

// channel-last transpose of x: [b][y][x][c]
__device__ __align__(16) float g_xt[4 * HW * 64];
// bf16-split deform weights: [k][o][c]
__device__ __align__(16) __nv_bfloat16 g_whi[9 * 64 * 64];
__device__ __align__(16) __nv_bfloat16 g_wlo[9 * 64 * 64];
// bf16-split offset-conv weights: [k][n(24)][c]
__device__ __align__(16) __nv_bfloat16 g_wohi[9 * NP * 64];
__device__ __align__(16) __nv_bfloat16 g_wolo[9 * NP * 64];

// ---------------- helpers ----------------
__device__ __forceinline__ u64 pack2(float lo, float hi) {
    u64 r;
    asm("mov.b64 %0, {%1, %2};" : "=l"(r) : "f"(lo), "f"(hi));
    return r;
}
__device__ __forceinline__ void unpack2(u64 v, float& lo, float& hi) {
    asm("mov.b64 {%0, %1}, %2;" : "=f"(lo), "=f"(hi) : "l"(v));
}
__device__ __forceinline__ u64 pack64(u32 a, u32 b) {
    return (u64)a | ((u64)b << 32);
}
__device__ __forceinline__ u32 smem_u32(const void* p) {
    u32 a;
    asm("{ .reg .u64 t; cvta.to.shared.u64 t, %1; cvt.u32.u64 %0, t; }"
        : "=r"(a) : "l"(p));
    return a;
}

#define SMEM_SWIZZLE_128B(o) ((o) ^ (((o) >> 3) & 0x70))

__device__ __forceinline__ void hmma(float* d, const u32* a, const u32* b) {
    asm volatile(
        "mma.sync.aligned.m16n8k16.row.col.f32.bf16.bf16.f32 "
        "{%0,%1,%2,%3}, {%4,%5,%6,%7}, {%8,%9}, {%0,%1,%2,%3};"
        : "+f"(d[0]), "+f"(d[1]), "+f"(d[2]), "+f"(d[3])
        : "r"(a[0]), "r"(a[1]), "r"(a[2]), "r"(a[3]), "r"(b[0]), "r"(b[1]));
}

__device__ __forceinline__ void ldsm_x4(u32* d, u32 addr) {
    asm volatile("ldmatrix.sync.aligned.m8n8.x4.shared.b16 {%0,%1,%2,%3}, [%4];"
        : "=r"(d[0]), "=r"(d[1]), "=r"(d[2]), "=r"(d[3]) : "r"(addr));
}
__device__ __forceinline__ void ldsm_x2(u32* d, u32 addr) {
    asm volatile("ldmatrix.sync.aligned.m8n8.x2.shared.b16 {%0,%1}, [%2];"
        : "=r"(d[0]), "=r"(d[1]) : "r"(addr));
}

__device__ __forceinline__ void split_bf16(float v, __nv_bfloat16& h, __nv_bfloat16& l) {
    h = __float2bfloat16(v);
    l = __float2bfloat16(v - __bfloat162float(h));
}
__device__ __forceinline__ void split2(float se, float so, u32& hh, u32& ll) {
    __nv_bfloat16 he, le, ho, lo2;
    split_bf16(se, he, le);
    split_bf16(so, ho, lo2);
    hh = (u32)__bfloat16_as_ushort(he) | ((u32)__bfloat16_as_ushort(ho) << 16);
    ll = (u32)__bfloat16_as_ushort(le) | ((u32)__bfloat16_as_ushort(lo2) << 16);
}

// ================= Kernel A: NCHW -> NHWC transpose of x =================
__global__ void __launch_bounds__(256)
transpose_kernel(const float* __restrict__ x) {
    __shared__ float tile[64 * 129];
    int row = blockIdx.x;               // b*128 + y
    int y = row & 127, b = row >> 7;
    const float* xb = x + (size_t)b * Cs * HW + y * Ws;
    int t = threadIdx.x;
    int w0 = t & 127, c0 = t >> 7;
#pragma unroll
    for (int i = 0; i < 32; i++) {
        int c = c0 + i * 2;
        tile[c * 129 + w0] = __ldg(xb + (size_t)c * HW + w0);
    }
    __syncthreads();
    float4* dst = (float4*)(g_xt + (size_t)row * 128 * 64);
#pragma unroll
    for (int i = 0; i < 8; i++) {
        int idx = t + i * 256;          // float4 index: idx = w*16 + cq
        int w = idx >> 4, cq = (idx & 15) * 4;
        float4 v;
        v.x = tile[cq * 129 + w];
        v.y = tile[(cq + 1) * 129 + w];
        v.z = tile[(cq + 2) * 129 + w];
        v.w = tile[(cq + 3) * 129 + w];
        dst[idx] = v;
    }
}

// ================= Kernel 0: split both weight sets to bf16 hi/lo =================
__global__ void wsplit_kernel(const float* __restrict__ wd,
                              const float* __restrict__ wo) {
    int i = blockIdx.x * 256 + threadIdx.x;
    if (i < 9 * 64 * 64) {
        int k = i >> 12;
        int r = i & 4095;
        int o = r >> 6;
        int c = r & 63;
        float v = wd[o * Q + c * 9 + k];
        __nv_bfloat16 h, l;
        split_bf16(v, h, l);
        g_whi[i] = h;
        g_wlo[i] = l;
    } else if (i < 9 * 64 * 64 + 9 * NP * 64) {
        int j = i - 9 * 64 * 64;
        int k = j / (NP * 64);
        int r = j - k * (NP * 64);
        int n = r >> 6;
        int c = r & 63;
        float v = (n < 18) ? wo[n * Q + c * 9 + k] : 0.0f;
        __nv_bfloat16 h, l;
        split_bf16(v, h, l);
        g_wohi[j] = h;
        g_wolo[j] = l;
    }
}

// ================= Fused kernel: double-buffered, 1 barrier per k =================
// SMEM (107520 B):
//   S buf0/1: hi @ buf*32768, lo @ buf*32768+16384   (65536 total)
//   W buf0/1: hi @ 65536+buf*16384, lo @ +8192       (32768 total)
//   OFF @ 98304 (9216)
static constexpr int SM_W0  = 65536;
static constexpr int SM_OFF = 98304;
static constexpr int SM_TOT = 107520;

__global__ void __launch_bounds__(256, 2)
fused_deform_kernel(const float* __restrict__ bo,
                    const float* __restrict__ bd,
                    float* __restrict__ out) {
    extern __shared__ __align__(1024) char smem[];
    u32 sb = smem_u32(smem);
    u64* offbuf = (u64*)(smem + SM_OFF);     // [9][128]

    int t    = threadIdx.x;
    int wid  = t >> 5;
    int lane = t & 31;
    int g    = lane >> 2;
    int tig  = lane & 3;

    int tile = blockIdx.x;
    int h = tile & 127;
    int b = tile >> 7;
    const float* xt = g_xt + (size_t)b * HW * 64;   // [y][x][c]

    int m0 = wid * 16;
    int p0 = t >> 4;          // sampler pixel base (0..15)
    int q4 = (t & 15) * 4;    // channel quad -> channel index

    int lr  = lane & 7;
    int lmi = lane >> 3;
    u32 aRow = (u32)((m0 + (lmi & 1) * 8 + lr) * 128);
    u32 aKof = (u32)((lmi >> 1) * 16);
    u32 bRow = (u32)(((lmi >> 1) * 8 + lr) * 128);
    u32 bKof = (u32)((lmi & 1) * 16);
    u32 b2Row = (u32)((16 + lr) * 128);
    u32 b2Kof = (u32)((lmi & 1) * 16);

    // ============ PHASE 1: offset conv (M=128, N=24, K=576) ============
    {
        float acc[3][4];
#pragma unroll
        for (int nt = 0; nt < 3; nt++)
#pragma unroll
            for (int j = 0; j < 4; j++) acc[nt][j] = 0.0f;

#pragma unroll 1
        for (int k = 0; k < 9; k++) {
            int sS = (k & 1) * 32768;            // S buf base
            int sW = SM_W0 + (k & 1) * 16384;    // W buf base

            if (t < 192) {
                int n  = t >> 3;
                int c8 = t & 7;
                u32 dst = SMEM_SWIZZLE_128B((u32)(n * 128 + c8 * 16));
                *(uint4*)(smem + sW + dst) =
                    *(const uint4*)(g_wohi + k * NP * 64 + n * 64 + c8 * 8);
                *(uint4*)(smem + sW + 8192 + dst) =
                    *(const uint4*)(g_wolo + k * NP * 64 + n * 64 + c8 * 8);
            }

            {
                int kh = k / 3, kw = k - kh * 3;
                int iy = h - 1 + kh;
                bool yok = (iy >= 0 && iy < Hs);
                int cy = min(max(iy, 0), Hs - 1);
                const float* xrow = xt + (size_t)cy * 128 * 64;
#pragma unroll
                for (int it = 0; it < 8; it++) {
                    int p = p0 + it * 16;
                    int ix = p - 1 + kw;
                    float vf = (yok && ix >= 0 && ix < Ws) ? 1.0f : 0.0f;
                    int cx = min(max(ix, 0), Ws - 1);
                    float4 v = *(const float4*)(xrow + cx * 64 + q4);
                    u32 hh0, ll0, hh1, ll1;
                    split2(v.x * vf, v.y * vf, hh0, ll0);
                    split2(v.z * vf, v.w * vf, hh1, ll1);
                    u32 off = SMEM_SWIZZLE_128B((u32)(p * 128 + q4 * 2));
                    *(u64*)(smem + sS + off)         = pack64(hh0, hh1);
                    *(u64*)(smem + sS + 16384 + off) = pack64(ll0, ll1);
                }
            }
            __syncthreads();

#pragma unroll
            for (int ks = 0; ks < 4; ks++) {
                u32 kb = (u32)(ks * 32);
                u32 ah[4], al[4];
                ldsm_x4(ah, sb + sS + SMEM_SWIZZLE_128B(aRow + kb + aKof));
                ldsm_x4(al, sb + sS + 16384 + SMEM_SWIZZLE_128B(aRow + kb + aKof));
                u32 bh[4], bl[4];
                ldsm_x4(bh, sb + sW + SMEM_SWIZZLE_128B(bRow + kb + bKof));
                ldsm_x4(bl, sb + sW + 8192 + SMEM_SWIZZLE_128B(bRow + kb + bKof));
                hmma(acc[0], ah, bh);     hmma(acc[0], ah, bl);     hmma(acc[0], al, bh);
                hmma(acc[1], ah, bh + 2); hmma(acc[1], ah, bl + 2); hmma(acc[1], al, bh + 2);
                u32 ch[2], cl[2];
                ldsm_x2(ch, sb + sW + SMEM_SWIZZLE_128B(b2Row + kb + b2Kof));
                ldsm_x2(cl, sb + sW + 8192 + SMEM_SWIZZLE_128B(b2Row + kb + b2Kof));
                hmma(acc[2], ah, ch);     hmma(acc[2], ah, cl);     hmma(acc[2], al, ch);
            }
            // no trailing barrier: next k writes the other buffer
        }
        __syncthreads();   // all GEMM reads done before O overlays buffer 0

        float* O = (float*)smem;       // [24 n][132 m]
#pragma unroll
        for (int nt = 0; nt < 3; nt++) {
            int n = nt * 8 + tig * 2;
            int m = m0 + g;
            O[n * 132 + m]            = acc[nt][0];
            O[(n + 1) * 132 + m]      = acc[nt][1];
            O[n * 132 + m + 8]        = acc[nt][2];
            O[(n + 1) * 132 + m + 8]  = acc[nt][3];
        }
        __syncthreads();

        for (int i = t; i < 9 * 128; i += 256) {
            int k2 = i >> 7;
            int m  = i & 127;
            float dy = O[(2 * k2) * 132 + m]     + __ldg(bo + 2 * k2);
            float dx = O[(2 * k2 + 1) * 132 + m] + __ldg(bo + 2 * k2 + 1);
            offbuf[k2 * 128 + m] = pack2(dy, dx);
        }
        __syncthreads();
    }

    // ============ PHASE 2: deformable conv (M=128, N=64, K=576) ============
    {
        float acc[8][4];
#pragma unroll
        for (int nt = 0; nt < 8; nt++)
#pragma unroll
            for (int j = 0; j < 4; j++) acc[nt][j] = 0.0f;

#pragma unroll 1
        for (int k = 0; k < 9; k++) {
            int sS = (k & 1) * 32768;
            int sW = SM_W0 + (k & 1) * 16384;

            for (int j = t; j < 512; j += 256) {
                int n  = j >> 3;
                int c8 = j & 7;
                u32 dst = SMEM_SWIZZLE_128B((u32)(n * 128 + c8 * 16));
                *(uint4*)(smem + sW + dst) =
                    *(const uint4*)(g_whi + k * 4096 + n * 64 + c8 * 8);
                *(uint4*)(smem + sW + 8192 + dst) =
                    *(const uint4*)(g_wlo + k * 4096 + n * 64 + c8 * 8);
            }

            {
                int kh = k / 3, kw = k - kh * 3;
                float hbase = (float)(h - 1 + kh);
#pragma unroll
                for (int it = 0; it < 8; it++) {
                    int p = p0 + it * 16;
                    float dlo, dhi;
                    unpack2(offbuf[k * 128 + p], dlo, dhi);
                    float py = hbase + dlo;
                    float px = (float)(p - 1 + kw) + dhi;
                    float y0f = floorf(py), x0f = floorf(px);
                    int y0 = (int)y0f, x0 = (int)x0f;
                    int y1 = y0 + 1,   x1 = x0 + 1;
                    float wy1 = py - y0f, wy0 = 1.0f - wy1;
                    float wx1 = px - x0f, wx0 = 1.0f - wx1;
                    float vy0 = (y0 >= 0 && y0 < Hs) ? 1.0f : 0.0f;
                    float vy1 = (y1 >= 0 && y1 < Hs) ? 1.0f : 0.0f;
                    float vx0 = (x0 >= 0 && x0 < Ws) ? 1.0f : 0.0f;
                    float vx1 = (x1 >= 0 && x1 < Ws) ? 1.0f : 0.0f;
                    float w00 = wy0 * wx0 * vy0 * vx0;
                    float w01 = wy0 * wx1 * vy0 * vx1;
                    float w10 = wy1 * wx0 * vy1 * vx0;
                    float w11 = wy1 * wx1 * vy1 * vx1;
                    int cy0 = min(max(y0, 0), Hs - 1), cy1 = min(max(y1, 0), Hs - 1);
                    int cx0 = min(max(x0, 0), Ws - 1), cx1 = min(max(x1, 0), Ws - 1);
                    const float* r0p = xt + (size_t)(cy0 * 128) * 64 + q4;
                    float4 ta = *(const float4*)(r0p + cx0 * 64);
                    float4 tb = *(const float4*)(r0p + cx1 * 64);
                    float s0 = fmaf(w00, ta.x, w01 * tb.x);
                    float s1 = fmaf(w00, ta.y, w01 * tb.y);
                    float s2 = fmaf(w00, ta.z, w01 * tb.z);
                    float s3 = fmaf(w00, ta.w, w01 * tb.w);
                    const float* r1p = xt + (size_t)(cy1 * 128) * 64 + q4;
                    ta = *(const float4*)(r1p + cx0 * 64);
                    tb = *(const float4*)(r1p + cx1 * 64);
                    s0 = fmaf(w10, ta.x, fmaf(w11, tb.x, s0));
                    s1 = fmaf(w10, ta.y, fmaf(w11, tb.y, s1));
                    s2 = fmaf(w10, ta.z, fmaf(w11, tb.z, s2));
                    s3 = fmaf(w10, ta.w, fmaf(w11, tb.w, s3));
                    u32 hh0, ll0, hh1, ll1;
                    split2(s0, s1, hh0, ll0);
                    split2(s2, s3, hh1, ll1);
                    u32 off = SMEM_SWIZZLE_128B((u32)(p * 128 + q4 * 2));
                    *(u64*)(smem + sS + off)         = pack64(hh0, hh1);
                    *(u64*)(smem + sS + 16384 + off) = pack64(ll0, ll1);
                }
            }
            __syncthreads();

#pragma unroll
            for (int ks = 0; ks < 4; ks++) {
                u32 kb = (u32)(ks * 32);
                u32 ah[4], al[4];
                ldsm_x4(ah, sb + sS + SMEM_SWIZZLE_128B(aRow + kb + aKof));
                ldsm_x4(al, sb + sS + 16384 + SMEM_SWIZZLE_128B(aRow + kb + aKof));
#pragma unroll
                for (int p = 0; p < 4; p++) {
                    u32 bh[4], bl[4];
                    u32 boff = SMEM_SWIZZLE_128B((u32)(p * 2048) + bRow + kb + bKof);
                    ldsm_x4(bh, sb + sW + boff);
                    ldsm_x4(bl, sb + sW + 8192 + boff);
                    hmma(acc[2 * p],     ah, bh);     hmma(acc[2 * p],     ah, bl);
                    hmma(acc[2 * p],     al, bh);
                    hmma(acc[2 * p + 1], ah, bh + 2); hmma(acc[2 * p + 1], ah, bl + 2);
                    hmma(acc[2 * p + 1], al, bh + 2);
                }
            }
            // no trailing barrier
        }
        __syncthreads();   // GEMM reads done before O overlays buffer 0

        float* O = (float*)smem;       // [64 n][132 m]
#pragma unroll
        for (int nt = 0; nt < 8; nt++) {
            int n = nt * 8 + tig * 2;
            int m = m0 + g;
            O[n * 132 + m]            = acc[nt][0];
            O[(n + 1) * 132 + m]      = acc[nt][1];
            O[n * 132 + m + 8]        = acc[nt][2];
            O[(n + 1) * 132 + m + 8]  = acc[nt][3];
        }
        __syncthreads();

        float* ob = out + (size_t)b * Os * HW + h * 128;
        for (int i = t; i < 64 * 128; i += 256) {
            int o  = i >> 7;
            int w2 = i & 127;
            ob[(size_t)o * HW + w2] = O[o * 132 + w2] + __ldg(bd + o);
        }
    }
}

// ---------------- harness entry ----------------
extern "C" void kernel_launch(void* const* d_in, const int* in_sizes, int n_in,
                              void* d_out, int out_size) {
    const float* x  = (const float*)d_in[0];   // [4,64,128,128]
    const float* wo = (const float*)d_in[1];   // [18,64,3,3]
    const float* bo = (const float*)d_in[2];   // [18]
    const float* wd = (const float*)d_in[3];   // [64,64,3,3]
    const float* bd = (const float*)d_in[4];   // [64]
    float* out = (float*)d_out;                // [4,64,128,128]

    cudaFuncSetAttribute(fused_deform_kernel,
                         cudaFuncAttributeMaxDynamicSharedMemorySize, SM_TOT);

    transpose_kernel<<<512, 256>>>(x);
    wsplit_kernel<<<198, 256>>>(wd, wo);
    fused_deform_kernel<<<512, 256, SM_TOT>>>(bo, bd, out);
}

// round 16
// speedup vs baseline: 1.1717x; 1.0501x over previous
#include <cuda_runtime.h>
#include <cuda_bf16.h>
#include <math.h>

#define Hs   128
#define Ws   128
#define Cs   64
#define Os   64
#define HW   16384
#define Q    576          // Cs * 9
#define NP   24           // padded N for offset conv

typedef unsigned long long u64;
typedef unsigned int u32;

// channel-last transpose of x: [b][y][x][c]
__device__ __align__(16) float g_xt[4 * HW * 64];
// bf16-split deform weights: [k][o][c]
__device__ __align__(16) __nv_bfloat16 g_whi[9 * 64 * 64];
__device__ __align__(16) __nv_bfloat16 g_wlo[9 * 64 * 64];
// bf16-split offset-conv weights: [k][n(24)][c]
__device__ __align__(16) __nv_bfloat16 g_wohi[9 * NP * 64];
__device__ __align__(16) __nv_bfloat16 g_wolo[9 * NP * 64];

// ---------------- helpers ----------------
__device__ __forceinline__ u64 pack2(float lo, float hi) {
    u64 r;
    asm("mov.b64 %0, {%1, %2};" : "=l"(r) : "f"(lo), "f"(hi));
    return r;
}
__device__ __forceinline__ void unpack2(u64 v, float& lo, float& hi) {
    asm("mov.b64 {%0, %1}, %2;" : "=f"(lo), "=f"(hi) : "l"(v));
}
__device__ __forceinline__ u64 pack64(u32 a, u32 b) {
    return (u64)a | ((u64)b << 32);
}
__device__ __forceinline__ u32 smem_u32(const void* p) {
    u32 a;
    asm("{ .reg .u64 t; cvta.to.shared.u64 t, %1; cvt.u32.u64 %0, t; }"
        : "=r"(a) : "l"(p));
    return a;
}

#define SMEM_SWIZZLE_128B(o) ((o) ^ (((o) >> 3) & 0x70))

__device__ __forceinline__ void hmma(float* d, const u32* a, const u32* b) {
    asm volatile(
        "mma.sync.aligned.m16n8k16.row.col.f32.bf16.bf16.f32 "
        "{%0,%1,%2,%3}, {%4,%5,%6,%7}, {%8,%9}, {%0,%1,%2,%3};"
        : "+f"(d[0]), "+f"(d[1]), "+f"(d[2]), "+f"(d[3])
        : "r"(a[0]), "r"(a[1]), "r"(a[2]), "r"(a[3]), "r"(b[0]), "r"(b[1]));
}

__device__ __forceinline__ void ldsm_x4(u32* d, u32 addr) {
    asm volatile("ldmatrix.sync.aligned.m8n8.x4.shared.b16 {%0,%1,%2,%3}, [%4];"
        : "=r"(d[0]), "=r"(d[1]), "=r"(d[2]), "=r"(d[3]) : "r"(addr));
}
__device__ __forceinline__ void ldsm_x2(u32* d, u32 addr) {
    asm volatile("ldmatrix.sync.aligned.m8n8.x2.shared.b16 {%0,%1}, [%2];"
        : "=r"(d[0]), "=r"(d[1]) : "r"(addr));
}

__device__ __forceinline__ void split_bf16(float v, __nv_bfloat16& h, __nv_bfloat16& l) {
    h = __float2bfloat16(v);
    l = __float2bfloat16(v - __bfloat162float(h));
}
__device__ __forceinline__ void split2(float se, float so, u32& hh, u32& ll) {
    __nv_bfloat16 he, le, ho, lo2;
    split_bf16(se, he, le);
    split_bf16(so, ho, lo2);
    hh = (u32)__bfloat16_as_ushort(he) | ((u32)__bfloat16_as_ushort(ho) << 16);
    ll = (u32)__bfloat16_as_ushort(le) | ((u32)__bfloat16_as_ushort(lo2) << 16);
}

// ================= Merged prep kernel: transpose (1024 blks) + wsplit (198 blks) =================
__global__ void __launch_bounds__(256)
prep_kernel(const float* __restrict__ x,
            const float* __restrict__ wd,
            const float* __restrict__ wo) {
    __shared__ float tile[32 * 129];
    int blk = blockIdx.x;
    int t = threadIdx.x;
    if (blk < 1024) {
        // transpose half-row: row = blk>>1, channel half = blk&1
        int row   = blk >> 1;
        int chalf = blk & 1;
        int y = row & 127, b = row >> 7;
        const float* xb = x + (size_t)b * Cs * HW + y * Ws + (size_t)(chalf * 32) * HW;
        int w0 = t & 127, cg = t >> 7;   // cg 0/1
#pragma unroll
        for (int i = 0; i < 16; i++) {
            int c = cg + i * 2;          // local channel 0..31
            tile[c * 129 + w0] = __ldg(xb + (size_t)c * HW + w0);
        }
        __syncthreads();
        float4* dst = (float4*)(g_xt + (size_t)row * 128 * 64);
#pragma unroll
        for (int i = 0; i < 4; i++) {
            int l = t + i * 256;         // 0..1023: l = w*8 + cql
            int w = l >> 3, cql = l & 7;
            float4 v;
            v.x = tile[(cql * 4)     * 129 + w];
            v.y = tile[(cql * 4 + 1) * 129 + w];
            v.z = tile[(cql * 4 + 2) * 129 + w];
            v.w = tile[(cql * 4 + 3) * 129 + w];
            dst[w * 16 + chalf * 8 + cql] = v;
        }
    } else {
        int i = (blk - 1024) * 256 + t;
        if (i < 9 * 64 * 64) {
            int k = i >> 12;
            int r = i & 4095;
            int o = r >> 6;
            int c = r & 63;
            float v = wd[o * Q + c * 9 + k];
            __nv_bfloat16 h2, l2;
            split_bf16(v, h2, l2);
            g_whi[i] = h2;
            g_wlo[i] = l2;
        } else if (i < 9 * 64 * 64 + 9 * NP * 64) {
            int j = i - 9 * 64 * 64;
            int k = j / (NP * 64);
            int r = j - k * (NP * 64);
            int n = r >> 6;
            int c = r & 63;
            float v = (n < 18) ? wo[n * Q + c * 9 + k] : 0.0f;
            __nv_bfloat16 h2, l2;
            split_bf16(v, h2, l2);
            g_wohi[j] = h2;
            g_wolo[j] = l2;
        }
    }
}

// ================= Fused kernel: offset conv + deformable conv (R13 layout) =================
static constexpr int SM_SHI = 0;
static constexpr int SM_SLO = 16384;
static constexpr int SM_WHI = 32768;
static constexpr int SM_WLO = 40960;
static constexpr int SM_OFF = 49152;
static constexpr int SM_TOT = 58368;

__global__ void __launch_bounds__(256, 2)
fused_deform_kernel(const float* __restrict__ bo,
                    const float* __restrict__ bd,
                    float* __restrict__ out) {
    extern __shared__ __align__(1024) char smem[];
    u32 sb = smem_u32(smem);
    u64* offbuf = (u64*)(smem + SM_OFF);     // [9][128]

    int t    = threadIdx.x;
    int wid  = t >> 5;
    int lane = t & 31;
    int g    = lane >> 2;
    int tig  = lane & 3;

    int tile = blockIdx.x;
    int h = tile & 127;
    int b = tile >> 7;
    const float* xt = g_xt + (size_t)b * HW * 64;   // [y][x][c]

    int m0 = wid * 16;
    int p0 = t >> 4;          // sampler pixel base (0..15)
    int q4 = (t & 15) * 4;    // channel quad -> channel index

    int lr  = lane & 7;
    int lmi = lane >> 3;
    u32 aRow = (u32)((m0 + (lmi & 1) * 8 + lr) * 128);
    u32 aKof = (u32)((lmi >> 1) * 16);
    u32 bRow = (u32)(((lmi >> 1) * 8 + lr) * 128);
    u32 bKof = (u32)((lmi & 1) * 16);
    u32 b2Row = (u32)((16 + lr) * 128);
    u32 b2Kof = (u32)((lmi & 1) * 16);

    // ============ PHASE 1: offset conv (M=128, N=24, K=576) ============
    {
        float acc[3][4];
#pragma unroll
        for (int nt = 0; nt < 3; nt++)
#pragma unroll
            for (int j = 0; j < 4; j++) acc[nt][j] = 0.0f;

#pragma unroll 1
        for (int k = 0; k < 9; k++) {
            if (t < 192) {
                int n  = t >> 3;
                int c8 = t & 7;
                u32 dst = SMEM_SWIZZLE_128B((u32)(n * 128 + c8 * 16));
                *(uint4*)(smem + SM_WHI + dst) =
                    *(const uint4*)(g_wohi + k * NP * 64 + n * 64 + c8 * 8);
                *(uint4*)(smem + SM_WLO + dst) =
                    *(const uint4*)(g_wolo + k * NP * 64 + n * 64 + c8 * 8);
            }

            {
                int kh = k / 3, kw = k - kh * 3;
                int iy = h - 1 + kh;
                bool yok = (iy >= 0 && iy < Hs);
                int cy = min(max(iy, 0), Hs - 1);
                const float* xrow = xt + (size_t)cy * 128 * 64;
#pragma unroll
                for (int it = 0; it < 8; it++) {
                    int p = p0 + it * 16;
                    int ix = p - 1 + kw;
                    float vf = (yok && ix >= 0 && ix < Ws) ? 1.0f : 0.0f;
                    int cx = min(max(ix, 0), Ws - 1);
                    float4 v = *(const float4*)(xrow + cx * 64 + q4);
                    u32 hh0, ll0, hh1, ll1;
                    split2(v.x * vf, v.y * vf, hh0, ll0);
                    split2(v.z * vf, v.w * vf, hh1, ll1);
                    u32 off = SMEM_SWIZZLE_128B((u32)(p * 128 + q4 * 2));
                    *(u64*)(smem + SM_SHI + off) = pack64(hh0, hh1);
                    *(u64*)(smem + SM_SLO + off) = pack64(ll0, ll1);
                }
            }
            __syncthreads();

#pragma unroll
            for (int ks = 0; ks < 4; ks++) {
                u32 kb = (u32)(ks * 32);
                u32 ah[4], al[4];
                ldsm_x4(ah, sb + SM_SHI + SMEM_SWIZZLE_128B(aRow + kb + aKof));
                ldsm_x4(al, sb + SM_SLO + SMEM_SWIZZLE_128B(aRow + kb + aKof));
                u32 bh[4], bl[4];
                ldsm_x4(bh, sb + SM_WHI + SMEM_SWIZZLE_128B(bRow + kb + bKof));
                ldsm_x4(bl, sb + SM_WLO + SMEM_SWIZZLE_128B(bRow + kb + bKof));
                hmma(acc[0], ah, bh);     hmma(acc[0], ah, bl);     hmma(acc[0], al, bh);
                hmma(acc[1], ah, bh + 2); hmma(acc[1], ah, bl + 2); hmma(acc[1], al, bh + 2);
                u32 ch[2], cl[2];
                ldsm_x2(ch, sb + SM_WHI + SMEM_SWIZZLE_128B(b2Row + kb + b2Kof));
                ldsm_x2(cl, sb + SM_WLO + SMEM_SWIZZLE_128B(b2Row + kb + b2Kof));
                hmma(acc[2], ah, ch);     hmma(acc[2], ah, cl);     hmma(acc[2], al, ch);
            }
            __syncthreads();
        }

        float* O = (float*)smem;       // [24 n][132 m]
#pragma unroll
        for (int nt = 0; nt < 3; nt++) {
            int n = nt * 8 + tig * 2;
            int m = m0 + g;
            O[n * 132 + m]            = acc[nt][0];
            O[(n + 1) * 132 + m]      = acc[nt][1];
            O[n * 132 + m + 8]        = acc[nt][2];
            O[(n + 1) * 132 + m + 8]  = acc[nt][3];
        }
        __syncthreads();

        for (int i = t; i < 9 * 128; i += 256) {
            int k2 = i >> 7;
            int m  = i & 127;
            float dy = O[(2 * k2) * 132 + m]     + __ldg(bo + 2 * k2);
            float dx = O[(2 * k2 + 1) * 132 + m] + __ldg(bo + 2 * k2 + 1);
            offbuf[k2 * 128 + m] = pack2(dy, dx);
        }
        __syncthreads();
    }

    // ============ PHASE 2: deformable conv (M=128, N=64, K=576) ============
    {
        float acc[8][4];
#pragma unroll
        for (int nt = 0; nt < 8; nt++)
#pragma unroll
            for (int j = 0; j < 4; j++) acc[nt][j] = 0.0f;

#pragma unroll 1
        for (int k = 0; k < 9; k++) {
            for (int j = t; j < 512; j += 256) {
                int n  = j >> 3;
                int c8 = j & 7;
                u32 dst = SMEM_SWIZZLE_128B((u32)(n * 128 + c8 * 16));
                *(uint4*)(smem + SM_WHI + dst) =
                    *(const uint4*)(g_whi + k * 4096 + n * 64 + c8 * 8);
                *(uint4*)(smem + SM_WLO + dst) =
                    *(const uint4*)(g_wlo + k * 4096 + n * 64 + c8 * 8);
            }

            {
                int kh = k / 3, kw = k - kh * 3;
                float hbase = (float)(h - 1 + kh);
#pragma unroll
                for (int it = 0; it < 8; it++) {
                    int p = p0 + it * 16;
                    float dlo, dhi;
                    unpack2(offbuf[k * 128 + p], dlo, dhi);
                    float py = hbase + dlo;
                    float px = (float)(p - 1 + kw) + dhi;
                    float y0f = floorf(py), x0f = floorf(px);
                    int y0 = (int)y0f, x0 = (int)x0f;
                    int y1 = y0 + 1,   x1 = x0 + 1;
                    float wy1 = py - y0f, wy0 = 1.0f - wy1;
                    float wx1 = px - x0f, wx0 = 1.0f - wx1;
                    float vy0 = (y0 >= 0 && y0 < Hs) ? 1.0f : 0.0f;
                    float vy1 = (y1 >= 0 && y1 < Hs) ? 1.0f : 0.0f;
                    float vx0 = (x0 >= 0 && x0 < Ws) ? 1.0f : 0.0f;
                    float vx1 = (x1 >= 0 && x1 < Ws) ? 1.0f : 0.0f;
                    float w00 = wy0 * wx0 * vy0 * vx0;
                    float w01 = wy0 * wx1 * vy0 * vx1;
                    float w10 = wy1 * wx0 * vy1 * vx0;
                    float w11 = wy1 * wx1 * vy1 * vx1;
                    int cy0 = min(max(y0, 0), Hs - 1), cy1 = min(max(y1, 0), Hs - 1);
                    int cx0 = min(max(x0, 0), Ws - 1), cx1 = min(max(x1, 0), Ws - 1);
                    const float* r0p = xt + (size_t)(cy0 * 128) * 64 + q4;
                    float4 ta = *(const float4*)(r0p + cx0 * 64);
                    float4 tb = *(const float4*)(r0p + cx1 * 64);
                    float s0 = fmaf(w00, ta.x, w01 * tb.x);
                    float s1 = fmaf(w00, ta.y, w01 * tb.y);
                    float s2 = fmaf(w00, ta.z, w01 * tb.z);
                    float s3 = fmaf(w00, ta.w, w01 * tb.w);
                    const float* r1p = xt + (size_t)(cy1 * 128) * 64 + q4;
                    ta = *(const float4*)(r1p + cx0 * 64);
                    tb = *(const float4*)(r1p + cx1 * 64);
                    s0 = fmaf(w10, ta.x, fmaf(w11, tb.x, s0));
                    s1 = fmaf(w10, ta.y, fmaf(w11, tb.y, s1));
                    s2 = fmaf(w10, ta.z, fmaf(w11, tb.z, s2));
                    s3 = fmaf(w10, ta.w, fmaf(w11, tb.w, s3));
                    u32 hh0, ll0, hh1, ll1;
                    split2(s0, s1, hh0, ll0);
                    split2(s2, s3, hh1, ll1);
                    u32 off = SMEM_SWIZZLE_128B((u32)(p * 128 + q4 * 2));
                    *(u64*)(smem + SM_SHI + off) = pack64(hh0, hh1);
                    *(u64*)(smem + SM_SLO + off) = pack64(ll0, ll1);
                }
            }
            __syncthreads();

#pragma unroll
            for (int ks = 0; ks < 4; ks++) {
                u32 kb = (u32)(ks * 32);
                u32 ah[4], al[4];
                ldsm_x4(ah, sb + SM_SHI + SMEM_SWIZZLE_128B(aRow + kb + aKof));
                ldsm_x4(al, sb + SM_SLO + SMEM_SWIZZLE_128B(aRow + kb + aKof));
#pragma unroll
                for (int p = 0; p < 4; p++) {
                    u32 bh[4], bl[4];
                    u32 boff = SMEM_SWIZZLE_128B((u32)(p * 2048) + bRow + kb + bKof);
                    ldsm_x4(bh, sb + SM_WHI + boff);
                    ldsm_x4(bl, sb + SM_WLO + boff);
                    hmma(acc[2 * p],     ah, bh);     hmma(acc[2 * p],     ah, bl);
                    hmma(acc[2 * p],     al, bh);
                    hmma(acc[2 * p + 1], ah, bh + 2); hmma(acc[2 * p + 1], ah, bl + 2);
                    hmma(acc[2 * p + 1], al, bh + 2);
                }
            }
            __syncthreads();
        }

        float* O = (float*)smem;       // [64 n][132 m]
#pragma unroll
        for (int nt = 0; nt < 8; nt++) {
            int n = nt * 8 + tig * 2;
            int m = m0 + g;
            O[n * 132 + m]            = acc[nt][0];
            O[(n + 1) * 132 + m]      = acc[nt][1];
            O[n * 132 + m + 8]        = acc[nt][2];
            O[(n + 1) * 132 + m + 8]  = acc[nt][3];
        }
        __syncthreads();

        float* ob = out + (size_t)b * Os * HW + h * 128;
        for (int i = t; i < 64 * 128; i += 256) {
            int o  = i >> 7;
            int w2 = i & 127;
            ob[(size_t)o * HW + w2] = O[o * 132 + w2] + __ldg(bd + o);
        }
    }
}

// ---------------- harness entry ----------------
extern "C" void kernel_launch(void* const* d_in, const int* in_sizes, int n_in,
                              void* d_out, int out_size) {
    const float* x  = (const float*)d_in[0];   // [4,64,128,128]
    const float* wo = (const float*)d_in[1];   // [18,64,3,3]
    const float* bo = (const float*)d_in[2];   // [18]
    const float* wd = (const float*)d_in[3];   // [64,64,3,3]
    const float* bd = (const float*)d_in[4];   // [64]
    float* out = (float*)d_out;                // [4,64,128,128]

    cudaFuncSetAttribute(fused_deform_kernel,
                         cudaFuncAttributeMaxDynamicSharedMemorySize, SM_TOT);

    prep_kernel<<<1222, 256>>>(x, wd, wo);
    fused_deform_kernel<<<512, 256, SM_TOT>>>(bo, bd, out);
}

// round 17
// speedup vs baseline: 1.2226x; 1.0435x over previous
#include <cuda_runtime.h>
#include <cuda_bf16.h>
#include <math.h>

#define Hs   128
#define Ws   128
#define Cs   64
#define Os   64
#define HW   16384
#define Q    576          // Cs * 9
#define NP   24           // padded N for offset conv

typedef unsigned long long u64;
typedef unsigned int u32;

// channel-last transpose of x: [b][y][x][c]
__device__ __align__(16) float g_xt[4 * HW * 64];
// bf16-split deform weights: [k][o][c]
__device__ __align__(16) __nv_bfloat16 g_whi[9 * 64 * 64];
__device__ __align__(16) __nv_bfloat16 g_wlo[9 * 64 * 64];
// bf16-split offset-conv weights: [k][n(24)][c]
__device__ __align__(16) __nv_bfloat16 g_wohi[9 * NP * 64];
__device__ __align__(16) __nv_bfloat16 g_wolo[9 * NP * 64];

// ---------------- helpers ----------------
__device__ __forceinline__ u64 pack2(float lo, float hi) {
    u64 r;
    asm("mov.b64 %0, {%1, %2};" : "=l"(r) : "f"(lo), "f"(hi));
    return r;
}
__device__ __forceinline__ void unpack2(u64 v, float& lo, float& hi) {
    asm("mov.b64 {%0, %1}, %2;" : "=f"(lo), "=f"(hi) : "l"(v));
}
__device__ __forceinline__ u64 pack64(u32 a, u32 b) {
    return (u64)a | ((u64)b << 32);
}
__device__ __forceinline__ u32 smem_u32(const void* p) {
    u32 a;
    asm("{ .reg .u64 t; cvta.to.shared.u64 t, %1; cvt.u32.u64 %0, t; }"
        : "=r"(a) : "l"(p));
    return a;
}

#define SMEM_SWIZZLE_128B(o) ((o) ^ (((o) >> 3) & 0x70))

__device__ __forceinline__ void hmma(float* d, const u32* a, const u32* b) {
    asm volatile(
        "mma.sync.aligned.m16n8k16.row.col.f32.bf16.bf16.f32 "
        "{%0,%1,%2,%3}, {%4,%5,%6,%7}, {%8,%9}, {%0,%1,%2,%3};"
        : "+f"(d[0]), "+f"(d[1]), "+f"(d[2]), "+f"(d[3])
        : "r"(a[0]), "r"(a[1]), "r"(a[2]), "r"(a[3]), "r"(b[0]), "r"(b[1]));
}

__device__ __forceinline__ void ldsm_x4(u32* d, u32 addr) {
    asm volatile("ldmatrix.sync.aligned.m8n8.x4.shared.b16 {%0,%1,%2,%3}, [%4];"
        : "=r"(d[0]), "=r"(d[1]), "=r"(d[2]), "=r"(d[3]) : "r"(addr));
}
__device__ __forceinline__ void ldsm_x2(u32* d, u32 addr) {
    asm volatile("ldmatrix.sync.aligned.m8n8.x2.shared.b16 {%0,%1}, [%2];"
        : "=r"(d[0]), "=r"(d[1]) : "r"(addr));
}

__device__ __forceinline__ void split_bf16(float v, __nv_bfloat16& h, __nv_bfloat16& l) {
    h = __float2bfloat16(v);
    l = __float2bfloat16(v - __bfloat162float(h));
}
__device__ __forceinline__ void split2(float se, float so, u32& hh, u32& ll) {
    __nv_bfloat16 he, le, ho, lo2;
    split_bf16(se, he, le);
    split_bf16(so, ho, lo2);
    hh = (u32)__bfloat16_as_ushort(he) | ((u32)__bfloat16_as_ushort(ho) << 16);
    ll = (u32)__bfloat16_as_ushort(le) | ((u32)__bfloat16_as_ushort(lo2) << 16);
}

// ================= Merged prep kernel: transpose (1024 blks) + wsplit (198 blks) =================
__global__ void __launch_bounds__(256)
prep_kernel(const float* __restrict__ x,
            const float* __restrict__ wd,
            const float* __restrict__ wo) {
    __shared__ float tile[32 * 129];
    int blk = blockIdx.x;
    int t = threadIdx.x;
    if (blk < 1024) {
        int row   = blk >> 1;
        int chalf = blk & 1;
        int y = row & 127, b = row >> 7;
        const float* xb = x + (size_t)b * Cs * HW + y * Ws + (size_t)(chalf * 32) * HW;
        int w0 = t & 127, cg = t >> 7;
#pragma unroll
        for (int i = 0; i < 16; i++) {
            int c = cg + i * 2;
            tile[c * 129 + w0] = __ldg(xb + (size_t)c * HW + w0);
        }
        __syncthreads();
        float4* dst = (float4*)(g_xt + (size_t)row * 128 * 64);
#pragma unroll
        for (int i = 0; i < 4; i++) {
            int l = t + i * 256;
            int w = l >> 3, cql = l & 7;
            float4 v;
            v.x = tile[(cql * 4)     * 129 + w];
            v.y = tile[(cql * 4 + 1) * 129 + w];
            v.z = tile[(cql * 4 + 2) * 129 + w];
            v.w = tile[(cql * 4 + 3) * 129 + w];
            dst[w * 16 + chalf * 8 + cql] = v;
        }
    } else {
        int i = (blk - 1024) * 256 + t;
        if (i < 9 * 64 * 64) {
            int k = i >> 12;
            int r = i & 4095;
            int o = r >> 6;
            int c = r & 63;
            float v = wd[o * Q + c * 9 + k];
            __nv_bfloat16 h2, l2;
            split_bf16(v, h2, l2);
            g_whi[i] = h2;
            g_wlo[i] = l2;
        } else if (i < 9 * 64 * 64 + 9 * NP * 64) {
            int j = i - 9 * 64 * 64;
            int k = j / (NP * 64);
            int r = j - k * (NP * 64);
            int n = r >> 6;
            int c = r & 63;
            float v = (n < 18) ? wo[n * Q + c * 9 + k] : 0.0f;
            __nv_bfloat16 h2, l2;
            split_bf16(v, h2, l2);
            g_wohi[j] = h2;
            g_wolo[j] = l2;
        }
    }
}

// ================= Fused kernel =================
static constexpr int SM_SHI = 0;
static constexpr int SM_SLO = 16384;
static constexpr int SM_WHI = 32768;
static constexpr int SM_WLO = 40960;
static constexpr int SM_OFF = 49152;    // 9216: offbuf
static constexpr int SM_PRM = 58368;    // 8192: params double buf [2][128][32B]
static constexpr int SM_TOT = 66560;

__global__ void __launch_bounds__(256, 2)
fused_deform_kernel(const float* __restrict__ bo,
                    const float* __restrict__ bd,
                    float* __restrict__ out) {
    extern __shared__ __align__(1024) char smem[];
    u32 sb = smem_u32(smem);
    u64* offbuf = (u64*)(smem + SM_OFF);     // [9][128]

    int t    = threadIdx.x;
    int wid  = t >> 5;
    int lane = t & 31;
    int g    = lane >> 2;
    int tig  = lane & 3;

    int tile = blockIdx.x;
    int h = tile & 127;
    int b = tile >> 7;
    const float* xt = g_xt + (size_t)b * HW * 64;   // [y][x][c]

    int m0 = wid * 16;
    int p0 = t >> 4;          // sampler pixel base (0..15)
    int q4 = (t & 15) * 4;    // channel quad -> channel index

    int lr  = lane & 7;
    int lmi = lane >> 3;
    u32 aRow = (u32)((m0 + (lmi & 1) * 8 + lr) * 128);
    u32 aKof = (u32)((lmi >> 1) * 16);
    u32 bRow = (u32)(((lmi >> 1) * 8 + lr) * 128);
    u32 bKof = (u32)((lmi & 1) * 16);
    u32 b2Row = (u32)((16 + lr) * 128);
    u32 b2Kof = (u32)((lmi & 1) * 16);

    // ============ PHASE 1: offset conv (M=128, N=24, K=576) ============
    {
        float acc[3][4];
#pragma unroll
        for (int nt = 0; nt < 3; nt++)
#pragma unroll
            for (int j = 0; j < 4; j++) acc[nt][j] = 0.0f;

#pragma unroll 1
        for (int k = 0; k < 9; k++) {
            if (t < 192) {
                int n  = t >> 3;
                int c8 = t & 7;
                u32 dst = SMEM_SWIZZLE_128B((u32)(n * 128 + c8 * 16));
                *(uint4*)(smem + SM_WHI + dst) =
                    *(const uint4*)(g_wohi + k * NP * 64 + n * 64 + c8 * 8);
                *(uint4*)(smem + SM_WLO + dst) =
                    *(const uint4*)(g_wolo + k * NP * 64 + n * 64 + c8 * 8);
            }

            {
                int kh = k / 3, kw = k - kh * 3;
                int iy = h - 1 + kh;
                bool yok = (iy >= 0 && iy < Hs);
                int cy = min(max(iy, 0), Hs - 1);
                const float* xrow = xt + (size_t)cy * 128 * 64;
#pragma unroll
                for (int it = 0; it < 8; it++) {
                    int p = p0 + it * 16;
                    int ix = p - 1 + kw;
                    float vf = (yok && ix >= 0 && ix < Ws) ? 1.0f : 0.0f;
                    int cx = min(max(ix, 0), Ws - 1);
                    float4 v = *(const float4*)(xrow + cx * 64 + q4);
                    u32 hh0, ll0, hh1, ll1;
                    split2(v.x * vf, v.y * vf, hh0, ll0);
                    split2(v.z * vf, v.w * vf, hh1, ll1);
                    u32 off = SMEM_SWIZZLE_128B((u32)(p * 128 + q4 * 2));
                    *(u64*)(smem + SM_SHI + off) = pack64(hh0, hh1);
                    *(u64*)(smem + SM_SLO + off) = pack64(ll0, ll1);
                }
            }
            __syncthreads();

#pragma unroll
            for (int ks = 0; ks < 4; ks++) {
                u32 kb = (u32)(ks * 32);
                u32 ah[4], al[4];
                ldsm_x4(ah, sb + SM_SHI + SMEM_SWIZZLE_128B(aRow + kb + aKof));
                ldsm_x4(al, sb + SM_SLO + SMEM_SWIZZLE_128B(aRow + kb + aKof));
                u32 bh[4], bl[4];
                ldsm_x4(bh, sb + SM_WHI + SMEM_SWIZZLE_128B(bRow + kb + bKof));
                ldsm_x4(bl, sb + SM_WLO + SMEM_SWIZZLE_128B(bRow + kb + bKof));
                hmma(acc[0], ah, bh);     hmma(acc[0], ah, bl);     hmma(acc[0], al, bh);
                hmma(acc[1], ah, bh + 2); hmma(acc[1], ah, bl + 2); hmma(acc[1], al, bh + 2);
                u32 ch[2], cl[2];
                ldsm_x2(ch, sb + SM_WHI + SMEM_SWIZZLE_128B(b2Row + kb + b2Kof));
                ldsm_x2(cl, sb + SM_WLO + SMEM_SWIZZLE_128B(b2Row + kb + b2Kof));
                hmma(acc[2], ah, ch);     hmma(acc[2], ah, cl);     hmma(acc[2], al, ch);
            }
            __syncthreads();
        }

        float* O = (float*)smem;       // [24 n][132 m]
#pragma unroll
        for (int nt = 0; nt < 3; nt++) {
            int n = nt * 8 + tig * 2;
            int m = m0 + g;
            O[n * 132 + m]            = acc[nt][0];
            O[(n + 1) * 132 + m]      = acc[nt][1];
            O[n * 132 + m + 8]        = acc[nt][2];
            O[(n + 1) * 132 + m + 8]  = acc[nt][3];
        }
        __syncthreads();

        for (int i = t; i < 9 * 128; i += 256) {
            int k2 = i >> 7;
            int m  = i & 127;
            float dy = O[(2 * k2) * 132 + m]     + __ldg(bo + 2 * k2);
            float dx = O[(2 * k2 + 1) * 132 + m] + __ldg(bo + 2 * k2 + 1);
            offbuf[k2 * 128 + m] = pack2(dy, dx);
        }
        __syncthreads();
    }

    // ============ PHASE 2: deformable conv (M=128, N=64, K=576) ============
    {
        float acc[8][4];
#pragma unroll
        for (int nt = 0; nt < 8; nt++)
#pragma unroll
            for (int j = 0; j < 4; j++) acc[nt][j] = 0.0f;

        // params(0) for pixels t<128
        if (t < 128) {
            int m = t;
            float dlo, dhi;
            unpack2(offbuf[m], dlo, dhi);
            float py = (float)(h - 1) + dlo;
            float px = (float)(m - 1) + dhi;
            float y0f = floorf(py), x0f = floorf(px);
            int y0 = (int)y0f, x0 = (int)x0f;
            int y1 = y0 + 1,   x1 = x0 + 1;
            float wy1 = py - y0f, wy0 = 1.0f - wy1;
            float wx1 = px - x0f, wx0 = 1.0f - wx1;
            float vy0 = (y0 >= 0 && y0 < Hs) ? 1.0f : 0.0f;
            float vy1 = (y1 >= 0 && y1 < Hs) ? 1.0f : 0.0f;
            float vx0 = (x0 >= 0 && x0 < Ws) ? 1.0f : 0.0f;
            float vx1 = (x1 >= 0 && x1 < Ws) ? 1.0f : 0.0f;
            int cy0 = min(max(y0, 0), Hs - 1), cy1 = min(max(y1, 0), Hs - 1);
            int cx0 = min(max(x0, 0), Ws - 1), cx1 = min(max(x1, 0), Ws - 1);
            char* pb = smem + SM_PRM + m * 32;
            *(float4*)pb = make_float4(wy0 * wx0 * vy0 * vx0, wy0 * wx1 * vy0 * vx1,
                                       wy1 * wx0 * vy1 * vx0, wy1 * wx1 * vy1 * vx1);
            *(int4*)(pb + 16) = make_int4((cy0 * 128 + cx0) * 64, (cy0 * 128 + cx1) * 64,
                                          (cy1 * 128 + cx0) * 64, (cy1 * 128 + cx1) * 64);
        }
        __syncthreads();

#pragma unroll 1
        for (int k = 0; k < 9; k++) {
            int prm = SM_PRM + (k & 1) * 4096;

            for (int j = t; j < 512; j += 256) {
                int n  = j >> 3;
                int c8 = j & 7;
                u32 dst = SMEM_SWIZZLE_128B((u32)(n * 128 + c8 * 16));
                *(uint4*)(smem + SM_WHI + dst) =
                    *(const uint4*)(g_whi + k * 4096 + n * 64 + c8 * 8);
                *(uint4*)(smem + SM_WLO + dst) =
                    *(const uint4*)(g_wlo + k * 4096 + n * 64 + c8 * 8);
            }

            // sampler: params from smem, 4 vector taps, split, STS
            {
                const float* q = xt + q4;
#pragma unroll
                for (int it = 0; it < 8; it++) {
                    int p = p0 + it * 16;
                    const char* pb = smem + prm + p * 32;
                    float4 wv = *(const float4*)pb;
                    int4  ov = *(const int4*)(pb + 16);
                    float4 ta = *(const float4*)(q + ov.x);
                    float4 tb = *(const float4*)(q + ov.y);
                    float s0 = fmaf(wv.x, ta.x, wv.y * tb.x);
                    float s1 = fmaf(wv.x, ta.y, wv.y * tb.y);
                    float s2 = fmaf(wv.x, ta.z, wv.y * tb.z);
                    float s3 = fmaf(wv.x, ta.w, wv.y * tb.w);
                    ta = *(const float4*)(q + ov.z);
                    tb = *(const float4*)(q + ov.w);
                    s0 = fmaf(wv.z, ta.x, fmaf(wv.w, tb.x, s0));
                    s1 = fmaf(wv.z, ta.y, fmaf(wv.w, tb.y, s1));
                    s2 = fmaf(wv.z, ta.z, fmaf(wv.w, tb.z, s2));
                    s3 = fmaf(wv.z, ta.w, fmaf(wv.w, tb.w, s3));
                    u32 hh0, ll0, hh1, ll1;
                    split2(s0, s1, hh0, ll0);
                    split2(s2, s3, hh1, ll1);
                    u32 off = SMEM_SWIZZLE_128B((u32)(p * 128 + q4 * 2));
                    *(u64*)(smem + SM_SHI + off) = pack64(hh0, hh1);
                    *(u64*)(smem + SM_SLO + off) = pack64(ll0, ll1);
                }
            }
            __syncthreads();

#pragma unroll
            for (int ks = 0; ks < 4; ks++) {
                u32 kb = (u32)(ks * 32);
                u32 ah[4], al[4];
                ldsm_x4(ah, sb + SM_SHI + SMEM_SWIZZLE_128B(aRow + kb + aKof));
                ldsm_x4(al, sb + SM_SLO + SMEM_SWIZZLE_128B(aRow + kb + aKof));
#pragma unroll
                for (int p = 0; p < 4; p++) {
                    u32 bh[4], bl[4];
                    u32 boff = SMEM_SWIZZLE_128B((u32)(p * 2048) + bRow + kb + bKof);
                    ldsm_x4(bh, sb + SM_WHI + boff);
                    ldsm_x4(bl, sb + SM_WLO + boff);
                    hmma(acc[2 * p],     ah, bh);     hmma(acc[2 * p],     ah, bl);
                    hmma(acc[2 * p],     al, bh);
                    hmma(acc[2 * p + 1], ah, bh + 2); hmma(acc[2 * p + 1], ah, bl + 2);
                    hmma(acc[2 * p + 1], al, bh + 2);
                }
            }

            // params(k+1) into the other buffer (overlaps GEMM issue window)
            if (k < 8 && t < 128) {
                int kk = k + 1;
                int kh = kk / 3, kw = kk - kh * 3;
                int m = t;
                float dlo, dhi;
                unpack2(offbuf[kk * 128 + m], dlo, dhi);
                float py = (float)(h - 1 + kh) + dlo;
                float px = (float)(m - 1 + kw) + dhi;
                float y0f = floorf(py), x0f = floorf(px);
                int y0 = (int)y0f, x0 = (int)x0f;
                int y1 = y0 + 1,   x1 = x0 + 1;
                float wy1 = py - y0f, wy0 = 1.0f - wy1;
                float wx1 = px - x0f, wx0 = 1.0f - wx1;
                float vy0 = (y0 >= 0 && y0 < Hs) ? 1.0f : 0.0f;
                float vy1 = (y1 >= 0 && y1 < Hs) ? 1.0f : 0.0f;
                float vx0 = (x0 >= 0 && x0 < Ws) ? 1.0f : 0.0f;
                float vx1 = (x1 >= 0 && x1 < Ws) ? 1.0f : 0.0f;
                int cy0 = min(max(y0, 0), Hs - 1), cy1 = min(max(y1, 0), Hs - 1);
                int cx0 = min(max(x0, 0), Ws - 1), cx1 = min(max(x1, 0), Ws - 1);
                char* pb = smem + SM_PRM + ((kk & 1) * 4096) + m * 32;
                *(float4*)pb = make_float4(wy0 * wx0 * vy0 * vx0, wy0 * wx1 * vy0 * vx1,
                                           wy1 * wx0 * vy1 * vx0, wy1 * wx1 * vy1 * vx1);
                *(int4*)(pb + 16) = make_int4((cy0 * 128 + cx0) * 64, (cy0 * 128 + cx1) * 64,
                                              (cy1 * 128 + cx0) * 64, (cy1 * 128 + cx1) * 64);
            }
            __syncthreads();
        }

        float* O = (float*)smem;       // [64 n][132 m]
#pragma unroll
        for (int nt = 0; nt < 8; nt++) {
            int n = nt * 8 + tig * 2;
            int m = m0 + g;
            O[n * 132 + m]            = acc[nt][0];
            O[(n + 1) * 132 + m]      = acc[nt][1];
            O[n * 132 + m + 8]        = acc[nt][2];
            O[(n + 1) * 132 + m + 8]  = acc[nt][3];
        }
        __syncthreads();

        float* ob = out + (size_t)b * Os * HW + h * 128;
        for (int i = t; i < 64 * 128; i += 256) {
            int o  = i >> 7;
            int w2 = i & 127;
            ob[(size_t)o * HW + w2] = O[o * 132 + w2] + __ldg(bd + o);
        }
    }
}

// ---------------- harness entry ----------------
extern "C" void kernel_launch(void* const* d_in, const int* in_sizes, int n_in,
                              void* d_out, int out_size) {
    const float* x  = (const float*)d_in[0];   // [4,64,128,128]
    const float* wo = (const float*)d_in[1];   // [18,64,3,3]
    const float* bo = (const float*)d_in[2];   // [18]
    const float* wd = (const float*)d_in[3];   // [64,64,3,3]
    const float* bd = (const float*)d_in[4];   // [64]
    float* out = (float*)d_out;                // [4,64,128,128]

    cudaFuncSetAttribute(fused_deform_kernel,
                         cudaFuncAttributeMaxDynamicSharedMemorySize, SM_TOT);

    prep_kernel<<<1222, 256>>>(x, wd, wo);
    fused_deform_kernel<<<512, 256, SM_TOT>>>(bo, bd, out);
}